// round 1
// baseline (speedup 1.0000x reference)
#include <cuda_runtime.h>
#include <cuda_bf16.h>
#include <cstdint>

// ---------------------------------------------------------------------------
// Problem constants
// ---------------------------------------------------------------------------
#define IMGS 24          // B*T
#define HWDIM 56
#define WSZ 7
#define WPS 8            // windows per side
#define NWIN (IMGS*WPS*WPS)     // 1536
#define NTOK 49
#define M_TOTAL (NWIN*NTOK)     // 75264
#define DMODEL 384
#define NHEAD 12
#define HD 32
#define QKV_N 1152

// ---------------------------------------------------------------------------
// Scratch (device globals; allocation is forbidden)
// ---------------------------------------------------------------------------
__device__ float g_xw [M_TOTAL * DMODEL];     // LN'd, window-partitioned input
__device__ float g_qkv[M_TOTAL * QKV_N];      // qkv projection
__device__ float g_att[M_TOTAL * DMODEL];     // attention output (window layout)

// ---------------------------------------------------------------------------
// Kernel 1: LayerNorm + window partition.  One block (96 threads) per token.
// Output row m is window-major: win = m/49 (img*64 + wy*8 + wx), n = m%49.
// ---------------------------------------------------------------------------
__global__ __launch_bounds__(96)
void ln_window_kernel(const float* __restrict__ x, const float* __restrict__ g,
                      const float* __restrict__ b, float* __restrict__ xw)
{
    int m = blockIdx.x;
    int win = m / NTOK, n = m - win * NTOK;
    int img = win >> 6;
    int wy  = (win >> 3) & 7;
    int wx  = win & 7;
    int iy = n / WSZ, ix = n - iy * WSZ;
    int h = wy * WSZ + iy;
    int w = wx * WSZ + ix;
    const float* xin = x + ((size_t)(img * HWDIM + h) * HWDIM + w) * DMODEL;

    int t = threadIdx.x;                 // 0..95, one float4 per thread
    float4 v = ((const float4*)xin)[t];
    float s  = v.x + v.y + v.z + v.w;
    float ss = v.x*v.x + v.y*v.y + v.z*v.z + v.w*v.w;
    #pragma unroll
    for (int off = 16; off; off >>= 1) {
        s  += __shfl_xor_sync(0xffffffffu, s,  off);
        ss += __shfl_xor_sync(0xffffffffu, ss, off);
    }
    __shared__ float sm[3], sm2[3];
    int wid = t >> 5, lane = t & 31;
    if (!lane) { sm[wid] = s; sm2[wid] = ss; }
    __syncthreads();
    s  = sm[0] + sm[1] + sm[2];
    ss = sm2[0] + sm2[1] + sm2[2];
    float mu  = s * (1.f / DMODEL);
    float var = ss * (1.f / DMODEL) - mu * mu;
    float rstd = rsqrtf(var + 1e-5f);

    float4 gg = ((const float4*)g)[t];
    float4 bb = ((const float4*)b)[t];
    float4 r;
    r.x = (v.x - mu) * rstd * gg.x + bb.x;
    r.y = (v.y - mu) * rstd * gg.y + bb.y;
    r.z = (v.z - mu) * rstd * gg.z + bb.z;
    r.w = (v.w - mu) * rstd * gg.w + bb.w;
    ((float4*)(xw + (size_t)m * DMODEL))[t] = r;
}

// ---------------------------------------------------------------------------
// SGEMM: C[M,NC] = A[M,384] @ W[384,NC] + bias, 128x128x8 tiles, 8x8 microtile.
// MODE 0: plain row-major store (qkv). MODE 1: un-window scatter into output.
// ---------------------------------------------------------------------------
template<int NC, int MODE>
__global__ __launch_bounds__(256)
void sgemm_k384(const float* __restrict__ A, const float* __restrict__ W,
                const float* __restrict__ bias, float* __restrict__ C)
{
    __shared__ float As[8][128];
    __shared__ float Bs[8][128];

    const int tid = threadIdx.x;
    const int m0 = blockIdx.y * 128;
    const int n0 = blockIdx.x * 128;

    const int arow = tid >> 1;            // 0..127
    const int acol = (tid & 1) * 4;       // 0 or 4
    const int brow = tid >> 5;            // 0..7
    const int bcol = (tid & 31) * 4;      // 0..124

    const int tx = tid & 15;              // col group
    const int ty = tid >> 4;              // row group

    const float* Aptr = A + (size_t)(m0 + arow) * DMODEL + acol;
    const float* Wptr = W + (size_t)brow * NC + n0 + bcol;

    float acc[8][8];
    #pragma unroll
    for (int i = 0; i < 8; i++)
        #pragma unroll
        for (int j = 0; j < 8; j++) acc[i][j] = 0.f;

    float4 aReg = *(const float4*)(Aptr);
    float4 bReg = *(const float4*)(Wptr);

    for (int kt = 0; kt < DMODEL / 8; kt++) {
        As[acol + 0][arow] = aReg.x;
        As[acol + 1][arow] = aReg.y;
        As[acol + 2][arow] = aReg.z;
        As[acol + 3][arow] = aReg.w;
        *(float4*)&Bs[brow][bcol] = bReg;
        __syncthreads();

        if (kt < DMODEL / 8 - 1) {
            aReg = *(const float4*)(Aptr + (kt + 1) * 8);
            bReg = *(const float4*)(Wptr + (size_t)(kt + 1) * 8 * NC);
        }

        #pragma unroll
        for (int k = 0; k < 8; k++) {
            float a[8], b[8];
            *(float4*)(a)     = *(const float4*)&As[k][ty * 4];
            *(float4*)(a + 4) = *(const float4*)&As[k][64 + ty * 4];
            *(float4*)(b)     = *(const float4*)&Bs[k][tx * 4];
            *(float4*)(b + 4) = *(const float4*)&Bs[k][64 + tx * 4];
            #pragma unroll
            for (int i = 0; i < 8; i++)
                #pragma unroll
                for (int j = 0; j < 8; j++)
                    acc[i][j] += a[i] * b[j];
        }
        __syncthreads();
    }

    // bias values for this thread's 8 columns
    float bl[8];
    #pragma unroll
    for (int jh = 0; jh < 2; jh++)
        #pragma unroll
        for (int j = 0; j < 4; j++)
            bl[jh * 4 + j] = __ldg(&bias[n0 + jh * 64 + tx * 4 + j]);

    #pragma unroll
    for (int ii = 0; ii < 8; ii++) {
        int row = (ii < 4) ? (ty * 4 + ii) : (64 + ty * 4 + ii - 4);
        int m = m0 + row;
        float* op;
        if (MODE == 0) {
            op = C + (size_t)m * NC + n0;
        } else {
            int win = m / NTOK, n = m - win * NTOK;
            int img = win >> 6;
            int wy = (win >> 3) & 7;
            int wx = win & 7;
            int iy = n / WSZ, ix = n - iy * WSZ;
            int ro = (img * HWDIM + wy * WSZ + iy) * HWDIM + wx * WSZ + ix;
            op = C + (size_t)ro * DMODEL + n0;
        }
        #pragma unroll
        for (int jh = 0; jh < 2; jh++) {
            float4 r;
            r.x = acc[ii][jh * 4 + 0] + bl[jh * 4 + 0];
            r.y = acc[ii][jh * 4 + 1] + bl[jh * 4 + 1];
            r.z = acc[ii][jh * 4 + 2] + bl[jh * 4 + 2];
            r.w = acc[ii][jh * 4 + 3] + bl[jh * 4 + 3];
            *(float4*)(op + jh * 64 + tx * 4) = r;
        }
    }
}

// ---------------------------------------------------------------------------
// Kernel 3: windowed attention.  One block per (window, head); 256 threads.
// q,k,v tiles 49x32 in smem (row stride 36 floats -> float4 column walks
// rotate bank quads, conflict-free). S[49][52] logits in smem.
// ---------------------------------------------------------------------------
__global__ __launch_bounds__(256)
void attn_kernel(const float* __restrict__ qkv, const float* __restrict__ bias_table,
                 float* __restrict__ attout)
{
    __shared__ float qs[NTOK * 36];
    __shared__ float ks[NTOK * 36];
    __shared__ float vs[NTOK * 36];
    __shared__ float S [NTOK * 52];
    __shared__ float sb[169];

    const int blk  = blockIdx.x;
    const int win  = blk / NHEAD;
    const int head = blk - win * NHEAD;
    const int tid  = threadIdx.x;
    const float scale = 0.17677669529663687f;   // 32^-0.5

    const size_t base = (size_t)win * NTOK * QKV_N + head * HD;

    // load q (pre-scaled), k, v
    for (int idx = tid; idx < NTOK * 8; idx += 256) {
        int n = idx >> 3, c = idx & 7;
        const float* p = qkv + base + (size_t)n * QKV_N + c * 4;
        float4 qv = *(const float4*)(p);
        qv.x *= scale; qv.y *= scale; qv.z *= scale; qv.w *= scale;
        *(float4*)&qs[n * 36 + c * 4] = qv;
        *(float4*)&ks[n * 36 + c * 4] = *(const float4*)(p + DMODEL);
        *(float4*)&vs[n * 36 + c * 4] = *(const float4*)(p + 2 * DMODEL);
    }
    for (int idx = tid; idx < 169; idx += 256)
        sb[idx] = bias_table[idx * NHEAD + head];
    __syncthreads();

    // S = q @ k^T + rel_bias
    for (int item = tid; item < 49 * 13; item += 256) {
        int i  = item / 13;
        int jq = item - i * 13;
        int j0 = jq * 4;
        float4 qv[8];
        #pragma unroll
        for (int c = 0; c < 8; c++) qv[c] = *(const float4*)&qs[i * 36 + c * 4];
        int iy = i / WSZ, ix = i - iy * WSZ;
        int nj = (j0 == 48) ? 1 : 4;
        for (int jj = 0; jj < nj; jj++) {
            int j = j0 + jj;
            float acc = 0.f;
            #pragma unroll
            for (int c = 0; c < 8; c++) {
                float4 kv = *(const float4*)&ks[j * 36 + c * 4];
                acc += qv[c].x * kv.x + qv[c].y * kv.y + qv[c].z * kv.z + qv[c].w * kv.w;
            }
            int jy = j / WSZ, jx = j - jy * WSZ;
            int ridx = (iy - jy + 6) * 13 + (ix - jx + 6);
            S[i * 52 + j] = acc + sb[ridx];
        }
    }
    __syncthreads();

    // row softmax (one warp per row)
    int wid = tid >> 5, lane = tid & 31;
    for (int r = wid; r < NTOK; r += 8) {
        float x1 = S[r * 52 + lane];
        float x2 = (lane + 32 < NTOK) ? S[r * 52 + lane + 32] : -1e30f;
        float mx = fmaxf(x1, x2);
        #pragma unroll
        for (int off = 16; off; off >>= 1)
            mx = fmaxf(mx, __shfl_xor_sync(0xffffffffu, mx, off));
        float e1 = __expf(x1 - mx);
        float e2 = (lane + 32 < NTOK) ? __expf(x2 - mx) : 0.f;
        float sum = e1 + e2;
        #pragma unroll
        for (int off = 16; off; off >>= 1)
            sum += __shfl_xor_sync(0xffffffffu, sum, off);
        float inv = 1.f / sum;
        S[r * 52 + lane] = e1 * inv;
        if (lane + 32 < NTOK) S[r * 52 + lane + 32] = e2 * inv;
    }
    __syncthreads();

    // out = P @ v  (items: 49 rows x 8 dquads)
    for (int item = tid; item < NTOK * 8; item += 256) {
        int i  = item >> 3;
        int dq = item & 7;
        float4 acc = make_float4(0.f, 0.f, 0.f, 0.f);
        #pragma unroll 7
        for (int j = 0; j < NTOK; j++) {
            float p = S[i * 52 + j];
            float4 vv = *(const float4*)&vs[j * 36 + dq * 4];
            acc.x += p * vv.x; acc.y += p * vv.y;
            acc.z += p * vv.z; acc.w += p * vv.w;
        }
        *(float4*)(attout + (size_t)(win * NTOK + i) * DMODEL + head * HD + dq * 4) = acc;
    }
}

// ---------------------------------------------------------------------------
// Launch
// ---------------------------------------------------------------------------
extern "C" void kernel_launch(void* const* d_in, const int* in_sizes, int n_in,
                              void* d_out, int out_size)
{
    const float* x      = (const float*)d_in[0];
    const float* ln_g   = (const float*)d_in[1];
    const float* ln_b   = (const float*)d_in[2];
    const float* qkv_w  = (const float*)d_in[3];
    const float* qkv_b  = (const float*)d_in[4];
    const float* proj_w = (const float*)d_in[5];
    const float* proj_b = (const float*)d_in[6];
    const float* relb   = (const float*)d_in[7];
    float* out = (float*)d_out;

    float *xw, *qkv, *att;
    cudaGetSymbolAddress((void**)&xw,  g_xw);
    cudaGetSymbolAddress((void**)&qkv, g_qkv);
    cudaGetSymbolAddress((void**)&att, g_att);

    ln_window_kernel<<<M_TOTAL, 96>>>(x, ln_g, ln_b, xw);
    sgemm_k384<QKV_N, 0><<<dim3(QKV_N / 128, M_TOTAL / 128), 256>>>(xw, qkv_w, qkv_b, qkv);
    attn_kernel<<<NWIN * NHEAD, 256>>>(qkv, relb, att);
    sgemm_k384<DMODEL, 1><<<dim3(DMODEL / 128, M_TOTAL / 128), 256>>>(att, proj_w, proj_b, out);
}

// round 2
// speedup vs baseline: 1.5720x; 1.5720x over previous
#include <cuda_runtime.h>
#include <cuda_bf16.h>
#include <cstdint>

// ---------------------------------------------------------------------------
// Problem constants
// ---------------------------------------------------------------------------
#define IMGS 24          // B*T
#define HWDIM 56
#define WSZ 7
#define NWIN (IMGS*64)          // 1536
#define NTOK 49
#define M_TOTAL (NWIN*NTOK)     // 75264
#define DMODEL 384
#define NHEAD 12
#define HD 32
#define QKV_N 1152
#define BK 16

// ---------------------------------------------------------------------------
// Scratch (device globals; allocation is forbidden)
// ---------------------------------------------------------------------------
__device__ float g_xw [M_TOTAL * DMODEL];     // LN'd, windowed, tf32-rounded
__device__ float g_qkv[M_TOTAL * QKV_N];      // qkv projection (fp32)
__device__ float g_att[M_TOTAL * DMODEL];     // attention out, tf32-rounded
__device__ float g_wq [DMODEL * QKV_N];       // tf32-rounded qkv_w
__device__ float g_wp [DMODEL * DMODEL];      // tf32-rounded proj_w

// ---------------------------------------------------------------------------
// Helpers
// ---------------------------------------------------------------------------
__device__ __forceinline__ float to_tf32(float x) {
    asm("cvt.rna.tf32.f32 %0, %0;" : "+f"(x));
    return x;
}

__device__ __forceinline__ void cp16(uint32_t dst, const void* src) {
    asm volatile("cp.async.cg.shared.global [%0], [%1], 16;\n" :: "r"(dst), "l"(src));
}

// exp(x) on the FMA pipe (avoids MUFU throughput wall).  rel err ~2e-6.
__device__ __forceinline__ float fast_exp(float x) {
    const float LOG2E = 1.4426950408889634f;
    float y0 = x * LOG2E;
    float t  = __fadd_rn(y0, 12582912.0f);          // round-to-nearest int
    int   n  = __float_as_int(t) - 0x4B400000;
    float fn = __fadd_rn(t, -12582912.0f);
    float f  = y0 - fn;                             // f in [-0.5, 0.5]
    float p  = 1.3333558e-3f;
    p = fmaf(p, f, 9.6181293e-3f);
    p = fmaf(p, f, 5.5504109e-2f);
    p = fmaf(p, f, 2.4022651e-1f);
    p = fmaf(p, f, 6.9314718e-1f);
    p = fmaf(p, f, 1.0f);
    n = max(n, -126);
    float s = __int_as_float((n + 127) << 23);
    return s * p;
}

// ---------------------------------------------------------------------------
// Kernel 0: round a weight matrix to tf32
// ---------------------------------------------------------------------------
__global__ void cvt_tf32_kernel(const float* __restrict__ src, float* __restrict__ dst, int n)
{
    int i = blockIdx.x * 256 + threadIdx.x;
    if (i < n) dst[i] = to_tf32(src[i]);
}

// ---------------------------------------------------------------------------
// Kernel 1: LayerNorm + window partition (tf32-rounded output)
// ---------------------------------------------------------------------------
__global__ __launch_bounds__(96)
void ln_window_kernel(const float* __restrict__ x, const float* __restrict__ g,
                      const float* __restrict__ b, float* __restrict__ xw)
{
    int m = blockIdx.x;
    int win = m / NTOK, n = m - win * NTOK;
    int img = win >> 6;
    int wy  = (win >> 3) & 7;
    int wx  = win & 7;
    int iy = n / WSZ, ix = n - iy * WSZ;
    int h = wy * WSZ + iy;
    int w = wx * WSZ + ix;
    const float* xin = x + ((size_t)(img * HWDIM + h) * HWDIM + w) * DMODEL;

    int t = threadIdx.x;                 // 0..95, one float4 per thread
    float4 v = ((const float4*)xin)[t];
    float s  = v.x + v.y + v.z + v.w;
    float ss = v.x*v.x + v.y*v.y + v.z*v.z + v.w*v.w;
    #pragma unroll
    for (int off = 16; off; off >>= 1) {
        s  += __shfl_xor_sync(0xffffffffu, s,  off);
        ss += __shfl_xor_sync(0xffffffffu, ss, off);
    }
    __shared__ float sm[3], sm2[3];
    int wid = t >> 5, lane = t & 31;
    if (!lane) { sm[wid] = s; sm2[wid] = ss; }
    __syncthreads();
    s  = sm[0] + sm[1] + sm[2];
    ss = sm2[0] + sm2[1] + sm2[2];
    float mu  = s * (1.f / DMODEL);
    float var = ss * (1.f / DMODEL) - mu * mu;
    float rstd = rsqrtf(var + 1e-5f);

    float4 gg = ((const float4*)g)[t];
    float4 bb = ((const float4*)b)[t];
    float4 r;
    r.x = to_tf32((v.x - mu) * rstd * gg.x + bb.x);
    r.y = to_tf32((v.y - mu) * rstd * gg.y + bb.y);
    r.z = to_tf32((v.z - mu) * rstd * gg.z + bb.z);
    r.w = to_tf32((v.w - mu) * rstd * gg.w + bb.w);
    ((float4*)(xw + (size_t)m * DMODEL))[t] = r;
}

// ---------------------------------------------------------------------------
// tf32 tensor-core GEMM: C[M,NC] = A[M,384] @ W[384,NC] + bias
// 128x128 block tile, BK=16, 8 warps (4Mx2N), m16n8k8 mma, cp.async 2-stage.
// MODE 0: row-major store.  MODE 1: un-window scatter.
// Operands must already be tf32-rounded.
// ---------------------------------------------------------------------------
template<int NC, int MODE>
__global__ __launch_bounds__(256, 2)
void mma_gemm(const float* __restrict__ A, const float* __restrict__ W,
              const float* __restrict__ bias, float* __restrict__ C)
{
    __shared__ float As[2][128 * 20];   // row stride 20 (conflict-free)
    __shared__ float Bs[2][BK * 136];   // row stride 136 (conflict-free)

    const int tid   = threadIdx.x;
    const int lane  = tid & 31;
    const int warp  = tid >> 5;
    const int mwarp = warp >> 1;        // 0..3
    const int nwarp = warp & 1;         // 0..1
    const int m0 = blockIdx.y * 128;
    const int n0 = blockIdx.x * 128;

    const uint32_t sA = (uint32_t)__cvta_generic_to_shared(&As[0][0]);
    const uint32_t sB = (uint32_t)__cvta_generic_to_shared(&Bs[0][0]);

    float c[2][8][4];
    #pragma unroll
    for (int i = 0; i < 2; i++)
        #pragma unroll
        for (int j = 0; j < 8; j++)
            #pragma unroll
            for (int q = 0; q < 4; q++) c[i][j][q] = 0.f;

    auto load_stage = [&](int kt, int buf) {
        int k0 = kt * BK;
        #pragma unroll
        for (int i = 0; i < 2; i++) {
            int idx = tid + i * 256;
            int ra = idx >> 2, ca = (idx & 3) * 4;          // A: 128 rows x 16
            cp16(sA + (buf * 2560 + ra * 20 + ca) * 4,
                 A + (size_t)(m0 + ra) * DMODEL + k0 + ca);
            int rb = idx >> 5, cb = (idx & 31) * 4;         // B: 16 rows x 128
            cp16(sB + (buf * (BK * 136) + rb * 136 + cb) * 4,
                 W + (size_t)(k0 + rb) * NC + n0 + cb);
        }
        asm volatile("cp.async.commit_group;\n");
    };

    load_stage(0, 0);

    const int KT = DMODEL / BK;   // 24
    for (int kt = 0; kt < KT; kt++) {
        int buf = kt & 1;
        if (kt + 1 < KT) {
            load_stage(kt + 1, buf ^ 1);
            asm volatile("cp.async.wait_group 1;\n" ::: "memory");
        } else {
            asm volatile("cp.async.wait_group 0;\n" ::: "memory");
        }
        __syncthreads();

        const float* Ab = &As[buf][0];
        const float* Bb = &Bs[buf][0];
        #pragma unroll
        for (int ks = 0; ks < 2; ks++) {
            int k = ks * 8;
            uint32_t a[2][4], b[8][2];
            #pragma unroll
            for (int mt = 0; mt < 2; mt++) {
                int r  = mwarp * 32 + mt * 16 + (lane >> 2);
                int cc = k + (lane & 3);
                a[mt][0] = __float_as_uint(Ab[r * 20 + cc]);
                a[mt][1] = __float_as_uint(Ab[(r + 8) * 20 + cc]);
                a[mt][2] = __float_as_uint(Ab[r * 20 + cc + 4]);
                a[mt][3] = __float_as_uint(Ab[(r + 8) * 20 + cc + 4]);
            }
            #pragma unroll
            for (int nt = 0; nt < 8; nt++) {
                int col = nwarp * 64 + nt * 8 + (lane >> 2);
                int kr  = k + (lane & 3);
                b[nt][0] = __float_as_uint(Bb[kr * 136 + col]);
                b[nt][1] = __float_as_uint(Bb[(kr + 4) * 136 + col]);
            }
            #pragma unroll
            for (int mt = 0; mt < 2; mt++)
                #pragma unroll
                for (int nt = 0; nt < 8; nt++)
                    asm volatile(
                        "mma.sync.aligned.m16n8k8.row.col.f32.tf32.tf32.f32 "
                        "{%0,%1,%2,%3}, {%4,%5,%6,%7}, {%8,%9}, {%0,%1,%2,%3};\n"
                        : "+f"(c[mt][nt][0]), "+f"(c[mt][nt][1]),
                          "+f"(c[mt][nt][2]), "+f"(c[mt][nt][3])
                        : "r"(a[mt][0]), "r"(a[mt][1]), "r"(a[mt][2]), "r"(a[mt][3]),
                          "r"(b[nt][0]), "r"(b[nt][1]));
        }
        __syncthreads();
    }

    // epilogue: bias + store (MODE 1 scatters to un-windowed layout)
    #pragma unroll
    for (int mt = 0; mt < 2; mt++) {
        #pragma unroll
        for (int half = 0; half < 2; half++) {
            int m = m0 + mwarp * 32 + mt * 16 + (lane >> 2) + half * 8;
            float* op;
            if (MODE == 0) {
                op = C + (size_t)m * NC;
            } else {
                int win = m / NTOK, n = m - win * NTOK;
                int img = win >> 6;
                int wy = (win >> 3) & 7;
                int wx = win & 7;
                int iy = n / WSZ, ix = n - iy * WSZ;
                int ro = (img * HWDIM + wy * WSZ + iy) * HWDIM + wx * WSZ + ix;
                op = C + (size_t)ro * DMODEL;
            }
            #pragma unroll
            for (int nt = 0; nt < 8; nt++) {
                int col = n0 + nwarp * 64 + nt * 8 + 2 * (lane & 3);
                float2 v;
                v.x = c[mt][nt][half * 2 + 0] + __ldg(&bias[col]);
                v.y = c[mt][nt][half * 2 + 1] + __ldg(&bias[col + 1]);
                *(float2*)(op + col) = v;
            }
        }
    }
}

// ---------------------------------------------------------------------------
// Kernel 3: windowed attention.  One block per (window, head); 256 threads.
// ---------------------------------------------------------------------------
__global__ __launch_bounds__(256)
void attn_kernel(const float* __restrict__ qkv, const float* __restrict__ bias_table,
                 float* __restrict__ attout)
{
    __shared__ float qs[NTOK * 36];
    __shared__ float ks[NTOK * 36];
    __shared__ float vs[NTOK * 36];
    __shared__ float S [NTOK * 52];
    __shared__ float sb[169];

    const int blk  = blockIdx.x;
    const int win  = blk / NHEAD;
    const int head = blk - win * NHEAD;
    const int tid  = threadIdx.x;
    const float scale = 0.17677669529663687f;   // 32^-0.5

    const size_t base = (size_t)win * NTOK * QKV_N + head * HD;

    for (int idx = tid; idx < NTOK * 8; idx += 256) {
        int n = idx >> 3, cq = idx & 7;
        const float* p = qkv + base + (size_t)n * QKV_N + cq * 4;
        float4 qv = *(const float4*)(p);
        qv.x *= scale; qv.y *= scale; qv.z *= scale; qv.w *= scale;
        *(float4*)&qs[n * 36 + cq * 4] = qv;
        *(float4*)&ks[n * 36 + cq * 4] = *(const float4*)(p + DMODEL);
        *(float4*)&vs[n * 36 + cq * 4] = *(const float4*)(p + 2 * DMODEL);
    }
    for (int idx = tid; idx < 169; idx += 256)
        sb[idx] = bias_table[idx * NHEAD + head];
    __syncthreads();

    // S = q @ k^T + rel_bias
    for (int item = tid; item < 49 * 13; item += 256) {
        int i  = item / 13;
        int jq = item - i * 13;
        int j0 = jq * 4;
        float4 qv[8];
        #pragma unroll
        for (int cq = 0; cq < 8; cq++) qv[cq] = *(const float4*)&qs[i * 36 + cq * 4];
        int iy = i / WSZ, ix = i - iy * WSZ;
        int nj = (j0 == 48) ? 1 : 4;
        for (int jj = 0; jj < nj; jj++) {
            int j = j0 + jj;
            float acc = 0.f;
            #pragma unroll
            for (int cq = 0; cq < 8; cq++) {
                float4 kv = *(const float4*)&ks[j * 36 + cq * 4];
                acc += qv[cq].x * kv.x + qv[cq].y * kv.y + qv[cq].z * kv.z + qv[cq].w * kv.w;
            }
            int jy = j / WSZ, jx = j - jy * WSZ;
            int ridx = (iy - jy + 6) * 13 + (ix - jx + 6);
            S[i * 52 + j] = acc + sb[ridx];
        }
    }
    __syncthreads();

    // row softmax (one warp per row), exp on the FMA pipe
    int wid = tid >> 5, lane = tid & 31;
    for (int r = wid; r < NTOK; r += 8) {
        float x1 = S[r * 52 + lane];
        float x2 = (lane + 32 < NTOK) ? S[r * 52 + lane + 32] : -1e30f;
        float mx = fmaxf(x1, x2);
        #pragma unroll
        for (int off = 16; off; off >>= 1)
            mx = fmaxf(mx, __shfl_xor_sync(0xffffffffu, mx, off));
        float e1 = fast_exp(x1 - mx);
        float e2 = (lane + 32 < NTOK) ? fast_exp(x2 - mx) : 0.f;
        float sum = e1 + e2;
        #pragma unroll
        for (int off = 16; off; off >>= 1)
            sum += __shfl_xor_sync(0xffffffffu, sum, off);
        float inv = 1.f / sum;
        S[r * 52 + lane] = e1 * inv;
        if (lane + 32 < NTOK) S[r * 52 + lane + 32] = e2 * inv;
    }
    __syncthreads();

    // out = P @ v, tf32-rounded for the downstream tensor-core proj GEMM
    for (int item = tid; item < NTOK * 8; item += 256) {
        int i  = item >> 3;
        int dq = item & 7;
        float4 acc = make_float4(0.f, 0.f, 0.f, 0.f);
        #pragma unroll 7
        for (int j = 0; j < NTOK; j++) {
            float p = S[i * 52 + j];
            float4 vv = *(const float4*)&vs[j * 36 + dq * 4];
            acc.x += p * vv.x; acc.y += p * vv.y;
            acc.z += p * vv.z; acc.w += p * vv.w;
        }
        acc.x = to_tf32(acc.x); acc.y = to_tf32(acc.y);
        acc.z = to_tf32(acc.z); acc.w = to_tf32(acc.w);
        *(float4*)(attout + (size_t)(win * NTOK + i) * DMODEL + head * HD + dq * 4) = acc;
    }
}

// ---------------------------------------------------------------------------
// Launch
// ---------------------------------------------------------------------------
extern "C" void kernel_launch(void* const* d_in, const int* in_sizes, int n_in,
                              void* d_out, int out_size)
{
    const float* x      = (const float*)d_in[0];
    const float* ln_g   = (const float*)d_in[1];
    const float* ln_b   = (const float*)d_in[2];
    const float* qkv_w  = (const float*)d_in[3];
    const float* qkv_b  = (const float*)d_in[4];
    const float* proj_w = (const float*)d_in[5];
    const float* proj_b = (const float*)d_in[6];
    const float* relb   = (const float*)d_in[7];
    float* out = (float*)d_out;

    float *xw, *qkv, *att, *wq, *wp;
    cudaGetSymbolAddress((void**)&xw,  g_xw);
    cudaGetSymbolAddress((void**)&qkv, g_qkv);
    cudaGetSymbolAddress((void**)&att, g_att);
    cudaGetSymbolAddress((void**)&wq,  g_wq);
    cudaGetSymbolAddress((void**)&wp,  g_wp);

    cvt_tf32_kernel<<<(DMODEL * QKV_N + 255) / 256, 256>>>(qkv_w, wq, DMODEL * QKV_N);
    cvt_tf32_kernel<<<(DMODEL * DMODEL + 255) / 256, 256>>>(proj_w, wp, DMODEL * DMODEL);
    ln_window_kernel<<<M_TOTAL, 96>>>(x, ln_g, ln_b, xw);
    mma_gemm<QKV_N, 0><<<dim3(QKV_N / 128, M_TOTAL / 128), 256>>>(xw, wq, qkv_b, qkv);
    attn_kernel<<<NWIN * NHEAD, 256>>>(qkv, relb, att);
    mma_gemm<DMODEL, 1><<<dim3(DMODEL / 128, M_TOTAL / 128), 256>>>(att, wp, proj_b, out);
}

// round 3
// speedup vs baseline: 3.0783x; 1.9582x over previous
#include <cuda_runtime.h>
#include <cuda_bf16.h>
#include <cstdint>

// ---------------------------------------------------------------------------
// Problem constants
// ---------------------------------------------------------------------------
#define IMGS 24          // B*T
#define HWDIM 56
#define WSZ 7
#define NWIN (IMGS*64)          // 1536
#define NTOK 49
#define M_TOTAL (NWIN*NTOK)     // 75264
#define DMODEL 384
#define NHEAD 12
#define HD 32
#define QKV_N 1152
#define BK 16
#define STAGES 3
#define A_STG (128*20)
#define B_STG (BK*136)

// ---------------------------------------------------------------------------
// Scratch (device globals; allocation is forbidden)
// ---------------------------------------------------------------------------
__device__ float g_xw [M_TOTAL * DMODEL];     // LN'd, windowed, tf32-rounded
__device__ float g_qkv[M_TOTAL * QKV_N];      // qkv projection (fp32)
__device__ float g_att[M_TOTAL * DMODEL];     // attention out, tf32-rounded
__device__ float g_wq [DMODEL * QKV_N];       // tf32-rounded qkv_w
__device__ float g_wp [DMODEL * DMODEL];      // tf32-rounded proj_w

// ---------------------------------------------------------------------------
// Helpers
// ---------------------------------------------------------------------------
__device__ __forceinline__ float to_tf32(float x) {
    asm("cvt.rna.tf32.f32 %0, %0;" : "+f"(x));
    return x;
}

__device__ __forceinline__ void cp16(uint32_t dst, const void* src) {
    asm volatile("cp.async.cg.shared.global [%0], [%1], 16;\n" :: "r"(dst), "l"(src));
}

// exp(x) on the FMA pipe.  rel err ~2e-6.  Safe for very negative x (->~0).
__device__ __forceinline__ float fast_exp(float x) {
    const float LOG2E = 1.4426950408889634f;
    float y0 = x * LOG2E;
    float t  = __fadd_rn(y0, 12582912.0f);
    int   n  = __float_as_int(t) - 0x4B400000;
    float fn = __fadd_rn(t, -12582912.0f);
    float f  = y0 - fn;
    float p  = 1.3333558e-3f;
    p = fmaf(p, f, 9.6181293e-3f);
    p = fmaf(p, f, 5.5504109e-2f);
    p = fmaf(p, f, 2.4022651e-1f);
    p = fmaf(p, f, 6.9314718e-1f);
    p = fmaf(p, f, 1.0f);
    n = max(n, -126);
    float s = __int_as_float((n + 127) << 23);
    return s * p;
}

#define MMA_TF32(C, A, B)                                                     \
    asm volatile(                                                             \
        "mma.sync.aligned.m16n8k8.row.col.f32.tf32.tf32.f32 "                 \
        "{%0,%1,%2,%3}, {%4,%5,%6,%7}, {%8,%9}, {%0,%1,%2,%3};\n"             \
        : "+f"((C)[0]), "+f"((C)[1]), "+f"((C)[2]), "+f"((C)[3])              \
        : "r"((A)[0]), "r"((A)[1]), "r"((A)[2]), "r"((A)[3]),                 \
          "r"((B)[0]), "r"((B)[1]))

// ---------------------------------------------------------------------------
// Kernel 0: round a weight matrix to tf32
// ---------------------------------------------------------------------------
__global__ void cvt_tf32_kernel(const float* __restrict__ src, float* __restrict__ dst, int n)
{
    int i = blockIdx.x * 256 + threadIdx.x;
    if (i < n) dst[i] = to_tf32(src[i]);
}

// ---------------------------------------------------------------------------
// Kernel 1: LayerNorm + window partition (tf32-rounded output)
// ---------------------------------------------------------------------------
__global__ __launch_bounds__(96)
void ln_window_kernel(const float* __restrict__ x, const float* __restrict__ g,
                      const float* __restrict__ b, float* __restrict__ xw)
{
    int m = blockIdx.x;
    int win = m / NTOK, n = m - win * NTOK;
    int img = win >> 6;
    int wy  = (win >> 3) & 7;
    int wx  = win & 7;
    int iy = n / WSZ, ix = n - iy * WSZ;
    int h = wy * WSZ + iy;
    int w = wx * WSZ + ix;
    const float* xin = x + ((size_t)(img * HWDIM + h) * HWDIM + w) * DMODEL;

    int t = threadIdx.x;
    float4 v = ((const float4*)xin)[t];
    float s  = v.x + v.y + v.z + v.w;
    float ss = v.x*v.x + v.y*v.y + v.z*v.z + v.w*v.w;
    #pragma unroll
    for (int off = 16; off; off >>= 1) {
        s  += __shfl_xor_sync(0xffffffffu, s,  off);
        ss += __shfl_xor_sync(0xffffffffu, ss, off);
    }
    __shared__ float sm[3], sm2[3];
    int wid = t >> 5, lane = t & 31;
    if (!lane) { sm[wid] = s; sm2[wid] = ss; }
    __syncthreads();
    s  = sm[0] + sm[1] + sm[2];
    ss = sm2[0] + sm2[1] + sm2[2];
    float mu  = s * (1.f / DMODEL);
    float var = ss * (1.f / DMODEL) - mu * mu;
    float rstd = rsqrtf(var + 1e-5f);

    float4 gg = ((const float4*)g)[t];
    float4 bb = ((const float4*)b)[t];
    float4 r;
    r.x = to_tf32((v.x - mu) * rstd * gg.x + bb.x);
    r.y = to_tf32((v.y - mu) * rstd * gg.y + bb.y);
    r.z = to_tf32((v.z - mu) * rstd * gg.z + bb.z);
    r.w = to_tf32((v.w - mu) * rstd * gg.w + bb.w);
    ((float4*)(xw + (size_t)m * DMODEL))[t] = r;
}

// ---------------------------------------------------------------------------
// tf32 tensor-core GEMM, 3-stage cp.async pipeline, dynamic smem.
// ---------------------------------------------------------------------------
template<int NC, int MODE>
__global__ __launch_bounds__(256, 2)
void mma_gemm(const float* __restrict__ A, const float* __restrict__ W,
              const float* __restrict__ bias, float* __restrict__ C)
{
    extern __shared__ float smem[];
    float* As = smem;                       // STAGES * A_STG
    float* Bs = smem + STAGES * A_STG;      // STAGES * B_STG

    const int tid   = threadIdx.x;
    const int lane  = tid & 31;
    const int warp  = tid >> 5;
    const int mwarp = warp >> 1;
    const int nwarp = warp & 1;
    const int m0 = blockIdx.y * 128;
    const int n0 = blockIdx.x * 128;

    const uint32_t sA = (uint32_t)__cvta_generic_to_shared(As);
    const uint32_t sB = (uint32_t)__cvta_generic_to_shared(Bs);

    float c[2][8][4];
    #pragma unroll
    for (int i = 0; i < 2; i++)
        #pragma unroll
        for (int j = 0; j < 8; j++)
            #pragma unroll
            for (int q = 0; q < 4; q++) c[i][j][q] = 0.f;

    auto load_stage = [&](int kt, int buf) {
        int k0 = kt * BK;
        #pragma unroll
        for (int i = 0; i < 2; i++) {
            int idx = tid + i * 256;
            int ra = idx >> 2, ca = (idx & 3) * 4;
            cp16(sA + (buf * A_STG + ra * 20 + ca) * 4,
                 A + (size_t)(m0 + ra) * DMODEL + k0 + ca);
            int rb = idx >> 5, cb = (idx & 31) * 4;
            cp16(sB + (buf * B_STG + rb * 136 + cb) * 4,
                 W + (size_t)(k0 + rb) * NC + n0 + cb);
        }
        asm volatile("cp.async.commit_group;\n");
    };

    load_stage(0, 0);
    load_stage(1, 1);

    const int KT = DMODEL / BK;   // 24
    for (int kt = 0; kt < KT; kt++) {
        int buf = kt % STAGES;
        if (kt + 2 < KT) {
            load_stage(kt + 2, (kt + 2) % STAGES);
            asm volatile("cp.async.wait_group 2;\n" ::: "memory");
        } else if (kt + 1 < KT) {
            asm volatile("cp.async.wait_group 1;\n" ::: "memory");
        } else {
            asm volatile("cp.async.wait_group 0;\n" ::: "memory");
        }
        __syncthreads();

        const float* Ab = &As[buf * A_STG];
        const float* Bb = &Bs[buf * B_STG];
        #pragma unroll
        for (int ks = 0; ks < 2; ks++) {
            int k = ks * 8;
            uint32_t a[2][4], b[8][2];
            #pragma unroll
            for (int mt = 0; mt < 2; mt++) {
                int r  = mwarp * 32 + mt * 16 + (lane >> 2);
                int cc = k + (lane & 3);
                a[mt][0] = __float_as_uint(Ab[r * 20 + cc]);
                a[mt][1] = __float_as_uint(Ab[(r + 8) * 20 + cc]);
                a[mt][2] = __float_as_uint(Ab[r * 20 + cc + 4]);
                a[mt][3] = __float_as_uint(Ab[(r + 8) * 20 + cc + 4]);
            }
            #pragma unroll
            for (int nt = 0; nt < 8; nt++) {
                int col = nwarp * 64 + nt * 8 + (lane >> 2);
                int kr  = k + (lane & 3);
                b[nt][0] = __float_as_uint(Bb[kr * 136 + col]);
                b[nt][1] = __float_as_uint(Bb[(kr + 4) * 136 + col]);
            }
            #pragma unroll
            for (int mt = 0; mt < 2; mt++)
                #pragma unroll
                for (int nt = 0; nt < 8; nt++)
                    MMA_TF32(c[mt][nt], a[mt], b[nt]);
        }
        __syncthreads();
    }

    #pragma unroll
    for (int mt = 0; mt < 2; mt++) {
        #pragma unroll
        for (int half = 0; half < 2; half++) {
            int m = m0 + mwarp * 32 + mt * 16 + (lane >> 2) + half * 8;
            float* op;
            if (MODE == 0) {
                op = C + (size_t)m * NC;
            } else {
                int win = m / NTOK, n = m - win * NTOK;
                int img = win >> 6;
                int wy = (win >> 3) & 7;
                int wx = win & 7;
                int iy = n / WSZ, ix = n - iy * WSZ;
                int ro = (img * HWDIM + wy * WSZ + iy) * HWDIM + wx * WSZ + ix;
                op = C + (size_t)ro * DMODEL;
            }
            #pragma unroll
            for (int nt = 0; nt < 8; nt++) {
                int col = n0 + nwarp * 64 + nt * 8 + 2 * (lane & 3);
                float2 v;
                v.x = c[mt][nt][half * 2 + 0] + __ldg(&bias[col]);
                v.y = c[mt][nt][half * 2 + 1] + __ldg(&bias[col + 1]);
                *(float2*)(op + col) = v;
            }
        }
    }
}

// ---------------------------------------------------------------------------
// Kernel 3: tensor-core windowed attention.
// One block (128 threads, 4 warps) per (window, head).
// S = Q@K^T (M=64pad, N=56pad, K=32) via tf32 mma; softmax in C-fragments;
// P stored to smem (warp-private rows); out = P@V (K=56) via tf32 mma.
// ---------------------------------------------------------------------------
__global__ __launch_bounds__(128)
void attn_mma_kernel(const float* __restrict__ qkv, const float* __restrict__ bias_table,
                     float* __restrict__ attout)
{
    __shared__ float qs[64 * 36];   // rows 49..63 uninit (row-confined garbage)
    __shared__ float ks[56 * 36];   // rows 49..55 zeroed
    __shared__ float vs[56 * 40];   // rows 49..55 zeroed (stride 40: conflict-free b-frags)
    __shared__ float Ps[64 * 60];   // P matrix, tf32
    __shared__ float sb[169];

    const int blk  = blockIdx.x;
    const int win  = blk / NHEAD;
    const int head = blk - win * NHEAD;
    const int tid  = threadIdx.x;
    const int lane = tid & 31;
    const int warp = tid >> 5;
    const float scale = 0.17677669529663687f;

    const size_t base = (size_t)win * NTOK * QKV_N + head * HD;

    // ---- load q (scaled), k, v; tf32-rounded ----
    for (int idx = tid; idx < NTOK * 8; idx += 128) {
        int n = idx >> 3, cq = idx & 7;
        const float* p = qkv + base + (size_t)n * QKV_N + cq * 4;
        float4 qv = *(const float4*)(p);
        qv.x = to_tf32(qv.x * scale); qv.y = to_tf32(qv.y * scale);
        qv.z = to_tf32(qv.z * scale); qv.w = to_tf32(qv.w * scale);
        *(float4*)&qs[n * 36 + cq * 4] = qv;
        float4 kv = *(const float4*)(p + DMODEL);
        kv.x = to_tf32(kv.x); kv.y = to_tf32(kv.y);
        kv.z = to_tf32(kv.z); kv.w = to_tf32(kv.w);
        *(float4*)&ks[n * 36 + cq * 4] = kv;
        float4 vv = *(const float4*)(p + 2 * DMODEL);
        vv.x = to_tf32(vv.x); vv.y = to_tf32(vv.y);
        vv.z = to_tf32(vv.z); vv.w = to_tf32(vv.w);
        *(float4*)&vs[n * 40 + cq * 4] = vv;
    }
    if (tid < 56) {            // zero pad rows 49..55 (7 rows x 8 quads)
        int n = 49 + (tid >> 3), cq = tid & 7;
        *(float4*)&ks[n * 36 + cq * 4] = make_float4(0.f, 0.f, 0.f, 0.f);
        *(float4*)&vs[n * 40 + cq * 4] = make_float4(0.f, 0.f, 0.f, 0.f);
    }
    for (int idx = tid; idx < 169; idx += 128)
        sb[idx] = bias_table[idx * NHEAD + head];
    __syncthreads();

    // ---- S = q @ k^T : each warp computes 16 rows x 56 cols ----
    float cS[7][4];
    #pragma unroll
    for (int nt = 0; nt < 7; nt++)
        #pragma unroll
        for (int q = 0; q < 4; q++) cS[nt][q] = 0.f;

    const int r0 = warp * 16 + (lane >> 2);
    #pragma unroll
    for (int kt = 0; kt < 4; kt++) {
        int kk = kt * 8 + (lane & 3);
        uint32_t a[4];
        a[0] = __float_as_uint(qs[r0 * 36 + kk]);
        a[1] = __float_as_uint(qs[(r0 + 8) * 36 + kk]);
        a[2] = __float_as_uint(qs[r0 * 36 + kk + 4]);
        a[3] = __float_as_uint(qs[(r0 + 8) * 36 + kk + 4]);
        #pragma unroll
        for (int nt = 0; nt < 7; nt++) {
            int n = nt * 8 + (lane >> 2);
            uint32_t b[2];
            b[0] = __float_as_uint(ks[n * 36 + kk]);
            b[1] = __float_as_uint(ks[n * 36 + kk + 4]);
            MMA_TF32(cS[nt], a, b);
        }
    }

    // ---- bias + softmax per row (row lives in 4 lanes; 2 rows per thread) ----
    #pragma unroll
    for (int h = 0; h < 2; h++) {
        int r = r0 + 8 * h;
        bool rvalid = (r < NTOK);
        int iy = r / WSZ, ix = r - iy * WSZ;
        float vals[14];
        float mx = -1e30f;
        #pragma unroll
        for (int nt = 0; nt < 7; nt++) {
            #pragma unroll
            for (int q = 0; q < 2; q++) {
                int col = nt * 8 + 2 * (lane & 3) + q;
                float vv = -1e30f;
                if (rvalid && col < NTOK) {
                    int jy = col / WSZ, jx = col - jy * WSZ;
                    vv = cS[nt][2 * h + q] + sb[(iy - jy + 6) * 13 + (ix - jx + 6)];
                }
                vals[nt * 2 + q] = vv;
                mx = fmaxf(mx, vv);
            }
        }
        mx = fmaxf(mx, __shfl_xor_sync(0xffffffffu, mx, 1));
        mx = fmaxf(mx, __shfl_xor_sync(0xffffffffu, mx, 2));
        float sum = 0.f;
        #pragma unroll
        for (int i = 0; i < 14; i++) {
            float e = fast_exp(vals[i] - mx);
            vals[i] = e;
            sum += e;
        }
        sum += __shfl_xor_sync(0xffffffffu, sum, 1);
        sum += __shfl_xor_sync(0xffffffffu, sum, 2);
        float inv = 1.f / sum;
        #pragma unroll
        for (int nt = 0; nt < 7; nt++)
            #pragma unroll
            for (int q = 0; q < 2; q++) {
                int col = nt * 8 + 2 * (lane & 3) + q;
                Ps[r * 60 + col] = to_tf32(vals[nt * 2 + q] * inv);
            }
    }
    __syncwarp();   // Ps rows are warp-private; warp-level visibility suffices

    // ---- out = P @ V : each warp 16 rows x 32 dims, K = 56 ----
    float o[4][4];
    #pragma unroll
    for (int nt = 0; nt < 4; nt++)
        #pragma unroll
        for (int q = 0; q < 4; q++) o[nt][q] = 0.f;

    #pragma unroll
    for (int kt = 0; kt < 7; kt++) {
        int kk = kt * 8 + (lane & 3);
        uint32_t a[4];
        a[0] = __float_as_uint(Ps[r0 * 60 + kk]);
        a[1] = __float_as_uint(Ps[(r0 + 8) * 60 + kk]);
        a[2] = __float_as_uint(Ps[r0 * 60 + kk + 4]);
        a[3] = __float_as_uint(Ps[(r0 + 8) * 60 + kk + 4]);
        #pragma unroll
        for (int nt = 0; nt < 4; nt++) {
            int d = nt * 8 + (lane >> 2);
            uint32_t b[2];
            b[0] = __float_as_uint(vs[kk * 40 + d]);
            b[1] = __float_as_uint(vs[(kk + 4) * 40 + d]);
            MMA_TF32(o[nt], a, b);
        }
    }

    // ---- store (tf32-rounded for downstream proj GEMM) ----
    #pragma unroll
    for (int h = 0; h < 2; h++) {
        int r = r0 + 8 * h;
        if (r < NTOK) {
            float* op = attout + (size_t)(win * NTOK + r) * DMODEL + head * HD;
            #pragma unroll
            for (int nt = 0; nt < 4; nt++) {
                int col = nt * 8 + 2 * (lane & 3);
                float2 v;
                v.x = to_tf32(o[nt][2 * h + 0]);
                v.y = to_tf32(o[nt][2 * h + 1]);
                *(float2*)(op + col) = v;
            }
        }
    }
}

// ---------------------------------------------------------------------------
// Launch
// ---------------------------------------------------------------------------
extern "C" void kernel_launch(void* const* d_in, const int* in_sizes, int n_in,
                              void* d_out, int out_size)
{
    const float* x      = (const float*)d_in[0];
    const float* ln_g   = (const float*)d_in[1];
    const float* ln_b   = (const float*)d_in[2];
    const float* qkv_w  = (const float*)d_in[3];
    const float* qkv_b  = (const float*)d_in[4];
    const float* proj_w = (const float*)d_in[5];
    const float* proj_b = (const float*)d_in[6];
    const float* relb   = (const float*)d_in[7];
    float* out = (float*)d_out;

    float *xw, *qkv, *att, *wq, *wp;
    cudaGetSymbolAddress((void**)&xw,  g_xw);
    cudaGetSymbolAddress((void**)&qkv, g_qkv);
    cudaGetSymbolAddress((void**)&att, g_att);
    cudaGetSymbolAddress((void**)&wq,  g_wq);
    cudaGetSymbolAddress((void**)&wp,  g_wp);

    const int gemm_smem = STAGES * (A_STG + B_STG) * 4;   // 56832 B
    static int attr_set = 0;
    if (!attr_set) {
        cudaFuncSetAttribute(mma_gemm<QKV_N, 0>,
                             cudaFuncAttributeMaxDynamicSharedMemorySize, gemm_smem);
        cudaFuncSetAttribute(mma_gemm<DMODEL, 1>,
                             cudaFuncAttributeMaxDynamicSharedMemorySize, gemm_smem);
        attr_set = 1;
    }

    cvt_tf32_kernel<<<(DMODEL * QKV_N + 255) / 256, 256>>>(qkv_w, wq, DMODEL * QKV_N);
    cvt_tf32_kernel<<<(DMODEL * DMODEL + 255) / 256, 256>>>(proj_w, wp, DMODEL * DMODEL);
    ln_window_kernel<<<M_TOTAL, 96>>>(x, ln_g, ln_b, xw);
    mma_gemm<QKV_N, 0><<<dim3(QKV_N / 128, M_TOTAL / 128), 256, gemm_smem>>>(xw, wq, qkv_b, qkv);
    attn_mma_kernel<<<NWIN * NHEAD, 128>>>(qkv, relb, att);
    mma_gemm<DMODEL, 1><<<dim3(DMODEL / 128, M_TOTAL / 128), 256, gemm_smem>>>(att, wp, proj_b, out);
}

// round 4
// speedup vs baseline: 3.1458x; 1.0219x over previous
#include <cuda_runtime.h>
#include <cuda_bf16.h>
#include <cstdint>

// ---------------------------------------------------------------------------
// Problem constants
// ---------------------------------------------------------------------------
#define IMGS 24          // B*T
#define HWDIM 56
#define WSZ 7
#define NWIN (IMGS*64)          // 1536
#define NTOK 49
#define M_TOTAL (NWIN*NTOK)     // 75264
#define DMODEL 384
#define NHEAD 12
#define HD 32
#define QKV_N 1152
#define BK 16
#define STAGES 3
#define A_STG (128*20)
#define B_STG (BK*136)

// ---------------------------------------------------------------------------
// Scratch (device globals; allocation is forbidden)
// ---------------------------------------------------------------------------
__device__ float g_xw [M_TOTAL * DMODEL];     // LN'd, windowed, tf32-rounded
__device__ float g_qkv[M_TOTAL * QKV_N];      // qkv projection (fp32)
__device__ float g_att[M_TOTAL * DMODEL];     // attention out, tf32-rounded
__device__ float g_wq [DMODEL * QKV_N];       // tf32-rounded qkv_w
__device__ float g_wp [DMODEL * DMODEL];      // tf32-rounded proj_w

// ---------------------------------------------------------------------------
// Helpers
// ---------------------------------------------------------------------------
__device__ __forceinline__ float to_tf32(float x) {
    asm("cvt.rna.tf32.f32 %0, %0;" : "+f"(x));
    return x;
}

__device__ __forceinline__ void cp16(uint32_t dst, const void* src) {
    asm volatile("cp.async.cg.shared.global [%0], [%1], 16;\n" :: "r"(dst), "l"(src));
}

// exp(x) on the FMA pipe.  rel err ~2e-6.  Safe for very negative x (->~0).
__device__ __forceinline__ float fast_exp(float x) {
    const float LOG2E = 1.4426950408889634f;
    float y0 = x * LOG2E;
    float t  = __fadd_rn(y0, 12582912.0f);
    int   n  = __float_as_int(t) - 0x4B400000;
    float fn = __fadd_rn(t, -12582912.0f);
    float f  = y0 - fn;
    float p  = 1.3333558e-3f;
    p = fmaf(p, f, 9.6181293e-3f);
    p = fmaf(p, f, 5.5504109e-2f);
    p = fmaf(p, f, 2.4022651e-1f);
    p = fmaf(p, f, 6.9314718e-1f);
    p = fmaf(p, f, 1.0f);
    n = max(n, -126);
    float s = __int_as_float((n + 127) << 23);
    return s * p;
}

#define MMA_TF32(C, A, B)                                                     \
    asm volatile(                                                             \
        "mma.sync.aligned.m16n8k8.row.col.f32.tf32.tf32.f32 "                 \
        "{%0,%1,%2,%3}, {%4,%5,%6,%7}, {%8,%9}, {%0,%1,%2,%3};\n"             \
        : "+f"((C)[0]), "+f"((C)[1]), "+f"((C)[2]), "+f"((C)[3])              \
        : "r"((A)[0]), "r"((A)[1]), "r"((A)[2]), "r"((A)[3]),                 \
          "r"((B)[0]), "r"((B)[1]))

// ---------------------------------------------------------------------------
// Kernel 0: round a weight matrix to tf32
// ---------------------------------------------------------------------------
__global__ void cvt_tf32_kernel(const float* __restrict__ src, float* __restrict__ dst, int n)
{
    int i = blockIdx.x * 256 + threadIdx.x;
    if (i < n) dst[i] = to_tf32(src[i]);
}

// ---------------------------------------------------------------------------
// Kernel 1: LayerNorm + window partition (tf32-rounded output)
// ---------------------------------------------------------------------------
__global__ __launch_bounds__(96)
void ln_window_kernel(const float* __restrict__ x, const float* __restrict__ g,
                      const float* __restrict__ b, float* __restrict__ xw)
{
    int m = blockIdx.x;
    int win = m / NTOK, n = m - win * NTOK;
    int img = win >> 6;
    int wy  = (win >> 3) & 7;
    int wx  = win & 7;
    int iy = n / WSZ, ix = n - iy * WSZ;
    int h = wy * WSZ + iy;
    int w = wx * WSZ + ix;
    const float* xin = x + ((size_t)(img * HWDIM + h) * HWDIM + w) * DMODEL;

    int t = threadIdx.x;
    float4 v = ((const float4*)xin)[t];
    float s  = v.x + v.y + v.z + v.w;
    float ss = v.x*v.x + v.y*v.y + v.z*v.z + v.w*v.w;
    #pragma unroll
    for (int off = 16; off; off >>= 1) {
        s  += __shfl_xor_sync(0xffffffffu, s,  off);
        ss += __shfl_xor_sync(0xffffffffu, ss, off);
    }
    __shared__ float sm[3], sm2[3];
    int wid = t >> 5, lane = t & 31;
    if (!lane) { sm[wid] = s; sm2[wid] = ss; }
    __syncthreads();
    s  = sm[0] + sm[1] + sm[2];
    ss = sm2[0] + sm2[1] + sm2[2];
    float mu  = s * (1.f / DMODEL);
    float var = ss * (1.f / DMODEL) - mu * mu;
    float rstd = rsqrtf(var + 1e-5f);

    float4 gg = ((const float4*)g)[t];
    float4 bb = ((const float4*)b)[t];
    float4 r;
    r.x = to_tf32((v.x - mu) * rstd * gg.x + bb.x);
    r.y = to_tf32((v.y - mu) * rstd * gg.y + bb.y);
    r.z = to_tf32((v.z - mu) * rstd * gg.z + bb.z);
    r.w = to_tf32((v.w - mu) * rstd * gg.w + bb.w);
    ((float4*)(xw + (size_t)m * DMODEL))[t] = r;
}

// ---------------------------------------------------------------------------
// tf32 tensor-core GEMM, 3-stage cp.async pipeline, ONE barrier per K-iter:
//   loop kt: { wait_group; __syncthreads; cp.async(kt+2); compute(kt) }
// Buffer safety: stage kt+2 reuses buffer of kt-1, whose last reader finished
// before the barrier every warp just crossed.  Visibility: each warp waits its
// own cp.async groups before that barrier.
// ---------------------------------------------------------------------------
template<int NC, int MODE>
__global__ __launch_bounds__(256, 2)
void mma_gemm(const float* __restrict__ A, const float* __restrict__ W,
              const float* __restrict__ bias, float* __restrict__ C)
{
    extern __shared__ float smem[];
    float* As = smem;                       // STAGES * A_STG
    float* Bs = smem + STAGES * A_STG;      // STAGES * B_STG

    const int tid   = threadIdx.x;
    const int lane  = tid & 31;
    const int warp  = tid >> 5;
    const int mwarp = warp >> 1;
    const int nwarp = warp & 1;
    const int m0 = blockIdx.y * 128;
    const int n0 = blockIdx.x * 128;

    const uint32_t sA = (uint32_t)__cvta_generic_to_shared(As);
    const uint32_t sB = (uint32_t)__cvta_generic_to_shared(Bs);

    float c[2][8][4];
    #pragma unroll
    for (int i = 0; i < 2; i++)
        #pragma unroll
        for (int j = 0; j < 8; j++)
            #pragma unroll
            for (int q = 0; q < 4; q++) c[i][j][q] = 0.f;

    auto load_stage = [&](int kt, int buf) {
        int k0 = kt * BK;
        #pragma unroll
        for (int i = 0; i < 2; i++) {
            int idx = tid + i * 256;
            int ra = idx >> 2, ca = (idx & 3) * 4;
            cp16(sA + (buf * A_STG + ra * 20 + ca) * 4,
                 A + (size_t)(m0 + ra) * DMODEL + k0 + ca);
            int rb = idx >> 5, cb = (idx & 31) * 4;
            cp16(sB + (buf * B_STG + rb * 136 + cb) * 4,
                 W + (size_t)(k0 + rb) * NC + n0 + cb);
        }
        asm volatile("cp.async.commit_group;\n");
    };

    load_stage(0, 0);
    load_stage(1, 1);

    const int KT = DMODEL / BK;   // 24
    for (int kt = 0; kt < KT; kt++) {
        int buf = kt % STAGES;
        // wait for stage kt (leave at most the next stage in flight)
        if (kt + 1 < KT) {
            asm volatile("cp.async.wait_group 1;\n" ::: "memory");
        } else {
            asm volatile("cp.async.wait_group 0;\n" ::: "memory");
        }
        __syncthreads();
        if (kt + 2 < KT)
            load_stage(kt + 2, (kt + 2) % STAGES);

        const float* Ab = &As[buf * A_STG];
        const float* Bb = &Bs[buf * B_STG];
        #pragma unroll
        for (int ks = 0; ks < 2; ks++) {
            int k = ks * 8;
            uint32_t a[2][4], b[8][2];
            #pragma unroll
            for (int mt = 0; mt < 2; mt++) {
                int r  = mwarp * 32 + mt * 16 + (lane >> 2);
                int cc = k + (lane & 3);
                a[mt][0] = __float_as_uint(Ab[r * 20 + cc]);
                a[mt][1] = __float_as_uint(Ab[(r + 8) * 20 + cc]);
                a[mt][2] = __float_as_uint(Ab[r * 20 + cc + 4]);
                a[mt][3] = __float_as_uint(Ab[(r + 8) * 20 + cc + 4]);
            }
            #pragma unroll
            for (int nt = 0; nt < 8; nt++) {
                int col = nwarp * 64 + nt * 8 + (lane >> 2);
                int kr  = k + (lane & 3);
                b[nt][0] = __float_as_uint(Bb[kr * 136 + col]);
                b[nt][1] = __float_as_uint(Bb[(kr + 4) * 136 + col]);
            }
            #pragma unroll
            for (int mt = 0; mt < 2; mt++)
                #pragma unroll
                for (int nt = 0; nt < 8; nt++)
                    MMA_TF32(c[mt][nt], a[mt], b[nt]);
        }
    }

    #pragma unroll
    for (int mt = 0; mt < 2; mt++) {
        #pragma unroll
        for (int half = 0; half < 2; half++) {
            int m = m0 + mwarp * 32 + mt * 16 + (lane >> 2) + half * 8;
            float* op;
            if (MODE == 0) {
                op = C + (size_t)m * NC;
            } else {
                int win = m / NTOK, n = m - win * NTOK;
                int img = win >> 6;
                int wy = (win >> 3) & 7;
                int wx = win & 7;
                int iy = n / WSZ, ix = n - iy * WSZ;
                int ro = (img * HWDIM + wy * WSZ + iy) * HWDIM + wx * WSZ + ix;
                op = C + (size_t)ro * DMODEL;
            }
            #pragma unroll
            for (int nt = 0; nt < 8; nt++) {
                int col = n0 + nwarp * 64 + nt * 8 + 2 * (lane & 3);
                float2 v;
                v.x = c[mt][nt][half * 2 + 0] + __ldg(&bias[col]);
                v.y = c[mt][nt][half * 2 + 1] + __ldg(&bias[col + 1]);
                *(float2*)(op + col) = v;
            }
        }
    }
}

// ---------------------------------------------------------------------------
// Kernel 3: tensor-core windowed attention.
// One block (128 threads, 4 warps) per (window, head).
// ---------------------------------------------------------------------------
__global__ __launch_bounds__(128)
void attn_mma_kernel(const float* __restrict__ qkv, const float* __restrict__ bias_table,
                     float* __restrict__ attout)
{
    __shared__ float qs[64 * 36];   // rows 49..63 uninit (row-confined garbage)
    __shared__ float ks[56 * 36];   // rows 49..55 zeroed
    __shared__ float vs[56 * 40];   // rows 49..55 zeroed
    __shared__ float Ps[64 * 60];   // P matrix, tf32
    __shared__ float sb[169];

    const int blk  = blockIdx.x;
    const int win  = blk / NHEAD;
    const int head = blk - win * NHEAD;
    const int tid  = threadIdx.x;
    const int lane = tid & 31;
    const int warp = tid >> 5;
    const float scale = 0.17677669529663687f;

    const size_t base = (size_t)win * NTOK * QKV_N + head * HD;

    for (int idx = tid; idx < NTOK * 8; idx += 128) {
        int n = idx >> 3, cq = idx & 7;
        const float* p = qkv + base + (size_t)n * QKV_N + cq * 4;
        float4 qv = *(const float4*)(p);
        qv.x = to_tf32(qv.x * scale); qv.y = to_tf32(qv.y * scale);
        qv.z = to_tf32(qv.z * scale); qv.w = to_tf32(qv.w * scale);
        *(float4*)&qs[n * 36 + cq * 4] = qv;
        float4 kv = *(const float4*)(p + DMODEL);
        kv.x = to_tf32(kv.x); kv.y = to_tf32(kv.y);
        kv.z = to_tf32(kv.z); kv.w = to_tf32(kv.w);
        *(float4*)&ks[n * 36 + cq * 4] = kv;
        float4 vv = *(const float4*)(p + 2 * DMODEL);
        vv.x = to_tf32(vv.x); vv.y = to_tf32(vv.y);
        vv.z = to_tf32(vv.z); vv.w = to_tf32(vv.w);
        *(float4*)&vs[n * 40 + cq * 4] = vv;
    }
    if (tid < 56) {
        int n = 49 + (tid >> 3), cq = tid & 7;
        *(float4*)&ks[n * 36 + cq * 4] = make_float4(0.f, 0.f, 0.f, 0.f);
        *(float4*)&vs[n * 40 + cq * 4] = make_float4(0.f, 0.f, 0.f, 0.f);
    }
    for (int idx = tid; idx < 169; idx += 128)
        sb[idx] = bias_table[idx * NHEAD + head];
    __syncthreads();

    // ---- S = q @ k^T ----
    float cS[7][4];
    #pragma unroll
    for (int nt = 0; nt < 7; nt++)
        #pragma unroll
        for (int q = 0; q < 4; q++) cS[nt][q] = 0.f;

    const int r0 = warp * 16 + (lane >> 2);
    #pragma unroll
    for (int kt = 0; kt < 4; kt++) {
        int kk = kt * 8 + (lane & 3);
        uint32_t a[4];
        a[0] = __float_as_uint(qs[r0 * 36 + kk]);
        a[1] = __float_as_uint(qs[(r0 + 8) * 36 + kk]);
        a[2] = __float_as_uint(qs[r0 * 36 + kk + 4]);
        a[3] = __float_as_uint(qs[(r0 + 8) * 36 + kk + 4]);
        #pragma unroll
        for (int nt = 0; nt < 7; nt++) {
            int n = nt * 8 + (lane >> 2);
            uint32_t b[2];
            b[0] = __float_as_uint(ks[n * 36 + kk]);
            b[1] = __float_as_uint(ks[n * 36 + kk + 4]);
            MMA_TF32(cS[nt], a, b);
        }
    }

    // ---- bias + softmax per row ----
    #pragma unroll
    for (int h = 0; h < 2; h++) {
        int r = r0 + 8 * h;
        bool rvalid = (r < NTOK);
        int iy = r / WSZ, ix = r - iy * WSZ;
        float vals[14];
        float mx = -1e30f;
        #pragma unroll
        for (int nt = 0; nt < 7; nt++) {
            #pragma unroll
            for (int q = 0; q < 2; q++) {
                int col = nt * 8 + 2 * (lane & 3) + q;
                float vv = -1e30f;
                if (rvalid && col < NTOK) {
                    int jy = col / WSZ, jx = col - jy * WSZ;
                    vv = cS[nt][2 * h + q] + sb[(iy - jy + 6) * 13 + (ix - jx + 6)];
                }
                vals[nt * 2 + q] = vv;
                mx = fmaxf(mx, vv);
            }
        }
        mx = fmaxf(mx, __shfl_xor_sync(0xffffffffu, mx, 1));
        mx = fmaxf(mx, __shfl_xor_sync(0xffffffffu, mx, 2));
        float sum = 0.f;
        #pragma unroll
        for (int i = 0; i < 14; i++) {
            float e = fast_exp(vals[i] - mx);
            vals[i] = e;
            sum += e;
        }
        sum += __shfl_xor_sync(0xffffffffu, sum, 1);
        sum += __shfl_xor_sync(0xffffffffu, sum, 2);
        float inv = 1.f / sum;
        #pragma unroll
        for (int nt = 0; nt < 7; nt++)
            #pragma unroll
            for (int q = 0; q < 2; q++) {
                int col = nt * 8 + 2 * (lane & 3) + q;
                Ps[r * 60 + col] = to_tf32(vals[nt * 2 + q] * inv);
            }
    }
    __syncwarp();

    // ---- out = P @ V ----
    float o[4][4];
    #pragma unroll
    for (int nt = 0; nt < 4; nt++)
        #pragma unroll
        for (int q = 0; q < 4; q++) o[nt][q] = 0.f;

    #pragma unroll
    for (int kt = 0; kt < 7; kt++) {
        int kk = kt * 8 + (lane & 3);
        uint32_t a[4];
        a[0] = __float_as_uint(Ps[r0 * 60 + kk]);
        a[1] = __float_as_uint(Ps[(r0 + 8) * 60 + kk]);
        a[2] = __float_as_uint(Ps[r0 * 60 + kk + 4]);
        a[3] = __float_as_uint(Ps[(r0 + 8) * 60 + kk + 4]);
        #pragma unroll
        for (int nt = 0; nt < 4; nt++) {
            int d = nt * 8 + (lane >> 2);
            uint32_t b[2];
            b[0] = __float_as_uint(vs[kk * 40 + d]);
            b[1] = __float_as_uint(vs[(kk + 4) * 40 + d]);
            MMA_TF32(o[nt], a, b);
        }
    }

    #pragma unroll
    for (int h = 0; h < 2; h++) {
        int r = r0 + 8 * h;
        if (r < NTOK) {
            float* op = attout + (size_t)(win * NTOK + r) * DMODEL + head * HD;
            #pragma unroll
            for (int nt = 0; nt < 4; nt++) {
                int col = nt * 8 + 2 * (lane & 3);
                float2 v;
                v.x = to_tf32(o[nt][2 * h + 0]);
                v.y = to_tf32(o[nt][2 * h + 1]);
                *(float2*)(op + col) = v;
            }
        }
    }
}

// ---------------------------------------------------------------------------
// Launch
// ---------------------------------------------------------------------------
extern "C" void kernel_launch(void* const* d_in, const int* in_sizes, int n_in,
                              void* d_out, int out_size)
{
    const float* x      = (const float*)d_in[0];
    const float* ln_g   = (const float*)d_in[1];
    const float* ln_b   = (const float*)d_in[2];
    const float* qkv_w  = (const float*)d_in[3];
    const float* qkv_b  = (const float*)d_in[4];
    const float* proj_w = (const float*)d_in[5];
    const float* proj_b = (const float*)d_in[6];
    const float* relb   = (const float*)d_in[7];
    float* out = (float*)d_out;

    float *xw, *qkv, *att, *wq, *wp;
    cudaGetSymbolAddress((void**)&xw,  g_xw);
    cudaGetSymbolAddress((void**)&qkv, g_qkv);
    cudaGetSymbolAddress((void**)&att, g_att);
    cudaGetSymbolAddress((void**)&wq,  g_wq);
    cudaGetSymbolAddress((void**)&wp,  g_wp);

    const int gemm_smem = STAGES * (A_STG + B_STG) * 4;   // 56832 B
    static int attr_set = 0;
    if (!attr_set) {
        cudaFuncSetAttribute(mma_gemm<QKV_N, 0>,
                             cudaFuncAttributeMaxDynamicSharedMemorySize, gemm_smem);
        cudaFuncSetAttribute(mma_gemm<DMODEL, 1>,
                             cudaFuncAttributeMaxDynamicSharedMemorySize, gemm_smem);
        attr_set = 1;
    }

    cvt_tf32_kernel<<<(DMODEL * QKV_N + 255) / 256, 256>>>(qkv_w, wq, DMODEL * QKV_N);
    cvt_tf32_kernel<<<(DMODEL * DMODEL + 255) / 256, 256>>>(proj_w, wp, DMODEL * DMODEL);
    ln_window_kernel<<<M_TOTAL, 96>>>(x, ln_g, ln_b, xw);
    mma_gemm<QKV_N, 0><<<dim3(QKV_N / 128, M_TOTAL / 128), 256, gemm_smem>>>(xw, wq, qkv_b, qkv);
    attn_mma_kernel<<<NWIN * NHEAD, 128>>>(qkv, relb, att);
    mma_gemm<DMODEL, 1><<<dim3(DMODEL / 128, M_TOTAL / 128), 256, gemm_smem>>>(att, wp, proj_b, out);
}